// round 6
// baseline (speedup 1.0000x reference)
#include <cuda_runtime.h>
#include <cuda_bf16.h>
#include <mma.h>
#include <math.h>
#include <stdint.h>

using namespace nvcuda;

// ---------------- scratch (device globals; no allocations) ----------------
#define MAXN 76800
#define MAXE 768000
#define MAXNF (76800u * 216u)

__device__ float g_Y[MAXNF];
__device__ float g_A[MAXNF];
__device__ float g_B[MAXNF];
__device__ __align__(16) __nv_bfloat16 g_Ah[76800u * 160u];
__device__ __align__(16) __nv_bfloat16 g_Al[76800u * 160u];
__device__ __align__(16) __nv_bfloat16 g_Wh[160 * 384];
__device__ __align__(16) __nv_bfloat16 g_Wl[160 * 384];
__device__ float g_nrm[MAXN];
__device__ int   g_deg[MAXN];
__device__ int   g_cur[MAXN];
__device__ int   g_rowptr[MAXN + 1];
__device__ int   g_csr[MAXE];
__device__ int   g_bsum[128];
__device__ int   g_gcnt[256];
__device__ int   g_gptr[257];
__device__ float g_pool[256 * 312];
__device__ float g_fc1[256 * 1024];
__device__ float g_cat[256 * 256];
__device__ float g_head[256 * 512];

static inline int gdiv(int n, int d) { return (n + d - 1) / d; }
static inline int pad32(int x) { return (x + 31) & ~31; }
static inline int pad128(int x) { return (x + 127) & ~127; }

// ---------------- small utility kernels ----------------
__global__ void k_zero2i(int* a, int* b, int n) {
    int i = blockIdx.x * blockDim.x + threadIdx.x;
    if (i < n) { a[i] = 0; b[i] = 0; }
}

__global__ void k_zeroi(int* a, int n) {
    int i = blockIdx.x * blockDim.x + threadIdx.x;
    if (i < n) a[i] = 0;
}

__global__ void k_hist(const int* __restrict__ idx, int* __restrict__ acc, int n) {
    int i = blockIdx.x * blockDim.x + threadIdx.x;
    if (i < n) atomicAdd(&acc[idx[i]], 1);
}

__global__ void k_nrm(const int* __restrict__ deg, float* __restrict__ nrm, int n) {
    int i = blockIdx.x * blockDim.x + threadIdx.x;
    if (i < n) nrm[i] = rsqrtf((float)deg[i] + 1.f);
}

// ---- multi-block exclusive scan: phase 1 per-block scan + block totals ----
__global__ void k_scan_blk(const int* __restrict__ in, int* __restrict__ out,
                           int* __restrict__ bsum, int n) {
    __shared__ int wsum[32];
    int tid = threadIdx.x;
    int lane = tid & 31, wid = tid >> 5;
    int i = blockIdx.x * 1024 + tid;
    int v = (i < n) ? in[i] : 0;
    int s = v;
#pragma unroll
    for (int off = 1; off < 32; off <<= 1) {
        int t = __shfl_up_sync(0xffffffffu, s, off);
        if (lane >= off) s += t;
    }
    if (lane == 31) wsum[wid] = s;
    __syncthreads();
    if (wid == 0) {
        int ws = wsum[lane];
#pragma unroll
        for (int off = 1; off < 32; off <<= 1) {
            int t = __shfl_up_sync(0xffffffffu, ws, off);
            if (lane >= off) ws += t;
        }
        wsum[lane] = ws;
    }
    __syncthreads();
    int wofs = (wid > 0) ? wsum[wid - 1] : 0;
    int incl = wofs + s;
    if (i < n) out[i] = incl - v;
    if (tid == 1023) bsum[blockIdx.x] = incl;
}

// phase 2: scan block totals (nb <= 75), single block of 128
__global__ void k_scan_small(int* __restrict__ b, int nb) {
    __shared__ int wsum[4];
    int tid = threadIdx.x;
    int lane = tid & 31, wid = tid >> 5;
    int v = (tid < nb) ? b[tid] : 0;
    int s = v;
#pragma unroll
    for (int off = 1; off < 32; off <<= 1) {
        int t = __shfl_up_sync(0xffffffffu, s, off);
        if (lane >= off) s += t;
    }
    if (lane == 31) wsum[wid] = s;
    __syncthreads();
    if (tid == 0) {
        int c = 0;
        for (int w = 0; w < 4; w++) { int t = wsum[w]; wsum[w] = c; c += t; }
    }
    __syncthreads();
    int excl = wsum[wid] + s - v;
    __syncthreads();
    if (tid < nb) b[tid] = excl;
    if (tid == nb - 1) b[nb] = excl + v;  // total
}

// phase 3: add block offsets; write out[n] = total
__global__ void k_scan_add(int* __restrict__ out, const int* __restrict__ bsum,
                           int n, int nb) {
    int i = blockIdx.x * blockDim.x + threadIdx.x;
    if (i < n) out[i] += bsum[i >> 10];
    if (i == 0) out[n] = bsum[nb];
}

__global__ void k_fill(const int* __restrict__ src, const int* __restrict__ dst,
                       const int* __restrict__ rowptr, int* __restrict__ cur,
                       int* __restrict__ csr, int E) {
    int e = blockIdx.x * blockDim.x + threadIdx.x;
    if (e >= E) return;
    int d = dst[e];
    int p = rowptr[d] + atomicAdd(&cur[d], 1);
    csr[p] = src[e];
}

// ---------------- aggregation (fp32 out): y_i = nrm_i*(sum nrm_s x_s + nrm_i x_i) [+bias][relu]
template <int NF>
__global__ void k_agg(const float* __restrict__ x, const float* __restrict__ nrm,
                      const int* __restrict__ rowptr, const int* __restrict__ csr,
                      float* __restrict__ y, int N, int F,
                      const float* __restrict__ bias, int dorelu) {
    int warp = (blockIdx.x * blockDim.x + threadIdx.x) >> 5;
    int lane = threadIdx.x & 31;
    if (warp >= N) return;
    int beg = rowptr[warp], end = rowptr[warp + 1];
    float ni = nrm[warp];

    float acc[NF];
#pragma unroll
    for (int j = 0; j < NF; j++) acc[j] = 0.f;

    int e = beg;
    for (; e + 1 < end; e += 2) {
        int s0 = csr[e], s1 = csr[e + 1];
        float n0 = nrm[s0], n1 = nrm[s1];
        const float* x0 = x + (size_t)s0 * F;
        const float* x1 = x + (size_t)s1 * F;
#pragma unroll
        for (int j = 0; j < NF; j++) {
            int f = lane + 32 * j;
            if (f < F) acc[j] += x0[f] * n0 + x1[f] * n1;
        }
    }
    if (e < end) {
        int s0 = csr[e];
        float n0 = nrm[s0];
        const float* x0 = x + (size_t)s0 * F;
#pragma unroll
        for (int j = 0; j < NF; j++) {
            int f = lane + 32 * j;
            if (f < F) acc[j] += x0[f] * n0;
        }
    }
    const float* xi = x + (size_t)warp * F;
    float* yi = y + (size_t)warp * F;
#pragma unroll
    for (int j = 0; j < NF; j++) {
        int f = lane + 32 * j;
        if (f < F) {
            float v = ni * (acc[j] + ni * xi[f]);
            if (bias) v += bias[f];
            if (dorelu) v = fmaxf(v, 0.f);
            yi[f] = v;
        }
    }
}

static void launch_agg(const float* x, const float* nrm, const int* rp, const int* csr,
                       float* y, int N, int F, const float* bias, int dorelu) {
    int blocks = gdiv(N, 8);
    int nf = gdiv(F, 32);
    switch (nf) {
        case 2: k_agg<2><<<blocks, 256>>>(x, nrm, rp, csr, y, N, F, bias, dorelu); break;
        case 3: k_agg<3><<<blocks, 256>>>(x, nrm, rp, csr, y, N, F, bias, dorelu); break;
        case 4: k_agg<4><<<blocks, 256>>>(x, nrm, rp, csr, y, N, F, bias, dorelu); break;
        case 5: k_agg<5><<<blocks, 256>>>(x, nrm, rp, csr, y, N, F, bias, dorelu); break;
        default: k_agg<8><<<blocks, 256>>>(x, nrm, rp, csr, y, N, F, bias, dorelu); break;
    }
}

// ---------------- aggregation with split-bf16 output (for tensor-core GEMM input) ----
__device__ __forceinline__ void bf_split(float v, __nv_bfloat16& h, __nv_bfloat16& l) {
    h = __float2bfloat16_rn(v);
    l = __float2bfloat16_rn(v - __bfloat162float(h));
}

template <int NF>
__global__ void k_aggb(const float* __restrict__ x, const float* __restrict__ nrm,
                       const int* __restrict__ rowptr, const int* __restrict__ csr,
                       __nv_bfloat16* __restrict__ Ah, __nv_bfloat16* __restrict__ Al,
                       int N, int F, int Kp) {
    int warp = (blockIdx.x * blockDim.x + threadIdx.x) >> 5;
    int lane = threadIdx.x & 31;
    if (warp >= N) return;
    int beg = rowptr[warp], end = rowptr[warp + 1];
    float ni = nrm[warp];

    float acc[NF];
#pragma unroll
    for (int j = 0; j < NF; j++) acc[j] = 0.f;

    int e = beg;
    for (; e + 1 < end; e += 2) {
        int s0 = csr[e], s1 = csr[e + 1];
        float n0 = nrm[s0], n1 = nrm[s1];
        const float* x0 = x + (size_t)s0 * F;
        const float* x1 = x + (size_t)s1 * F;
#pragma unroll
        for (int j = 0; j < NF; j++) {
            int f = lane + 32 * j;
            if (f < F) acc[j] += x0[f] * n0 + x1[f] * n1;
        }
    }
    if (e < end) {
        int s0 = csr[e];
        float n0 = nrm[s0];
        const float* x0 = x + (size_t)s0 * F;
#pragma unroll
        for (int j = 0; j < NF; j++) {
            int f = lane + 32 * j;
            if (f < F) acc[j] += x0[f] * n0;
        }
    }
    const float* xi = x + (size_t)warp * F;
    __nv_bfloat16* ah = Ah + (size_t)warp * Kp;
    __nv_bfloat16* al = Al + (size_t)warp * Kp;
#pragma unroll
    for (int j = 0; j < NF; j++) {
        int f = lane + 32 * j;
        if (f < F) {
            float v = ni * (acc[j] + ni * xi[f]);
            __nv_bfloat16 h, l;
            bf_split(v, h, l);
            ah[f] = h; al[f] = l;
        }
    }
    for (int f = F + lane; f < Kp; f += 32) {
        ah[f] = __float2bfloat16_rn(0.f);
        al[f] = __float2bfloat16_rn(0.f);
    }
}

static void launch_aggb(const float* x, const float* nrm, const int* rp, const int* csr,
                        __nv_bfloat16* Ah, __nv_bfloat16* Al, int N, int F, int Kp) {
    int blocks = gdiv(N, 8);
    int nf = gdiv(F, 32);
    switch (nf) {
        case 2: k_aggb<2><<<blocks, 256>>>(x, nrm, rp, csr, Ah, Al, N, F, Kp); break;
        case 3: k_aggb<3><<<blocks, 256>>>(x, nrm, rp, csr, Ah, Al, N, F, Kp); break;
        case 4: k_aggb<4><<<blocks, 256>>>(x, nrm, rp, csr, Ah, Al, N, F, Kp); break;
        default: k_aggb<5><<<blocks, 256>>>(x, nrm, rp, csr, Ah, Al, N, F, Kp); break;
    }
}

// ---------------- weight split-convert with padding ----------------
__global__ void k_cvtW(const float* __restrict__ W, __nv_bfloat16* __restrict__ Wh,
                       __nv_bfloat16* __restrict__ Wl, int K, int M, int Kp, int Mp) {
    int idx = blockIdx.x * blockDim.x + threadIdx.x;
    if (idx >= Kp * Mp) return;
    int r = idx / Mp, c = idx - r * Mp;
    float v = (r < K && c < M) ? W[(size_t)r * M + c] : 0.f;
    __nv_bfloat16 h, l;
    bf_split(v, h, l);
    Wh[idx] = h; Wl[idx] = l;
}

// ---------------- split-bf16 tensor-core GEMM ----------------
// C[N,M] = A[N,Kp] @ W[Kp,Mp] (+bias, relu). A = Ah+Al, W = Wh+Wl (bf16 splits).
// N % 128 == 0, Kp % 32 == 0, Mp % 128 == 0 (zero-padded). Guards only on C cols.
// 256 threads = 8 warps (2m x 4n), warp tile 64x32, k-tile 32, cp.async 2-stage.
#define HG_SMEM_BYTES 75776

__device__ __forceinline__ void cp16(uint32_t sdst, const void* gsrc) {
    asm volatile("cp.async.cg.shared.global [%0], [%1], 16;\n" :: "r"(sdst), "l"(gsrc));
}
__device__ __forceinline__ void cp_commit() {
    asm volatile("cp.async.commit_group;\n");
}
template <int NN>
__device__ __forceinline__ void cp_wait() {
    asm volatile("cp.async.wait_group %0;\n" :: "n"(NN));
}

__global__ __launch_bounds__(256) void k_hgemm(
    const __nv_bfloat16* __restrict__ Ah, const __nv_bfloat16* __restrict__ Al,
    const __nv_bfloat16* __restrict__ Wh, const __nv_bfloat16* __restrict__ Wl,
    const float* __restrict__ bias, float* __restrict__ C,
    int N, int Kp, int Mp, int M, int ldc, int relu)
{
    extern __shared__ __align__(16) char dynsm[];
    // layout (bf16 elems): sAh[2][128*40], sAl[2][128*40], sBh[2][32*136], sBl[2][32*136]
    __nv_bfloat16* sAh = (__nv_bfloat16*)dynsm;
    __nv_bfloat16* sAl = sAh + 2 * 5120;
    __nv_bfloat16* sBh = sAl + 2 * 5120;
    __nv_bfloat16* sBl = sBh + 2 * 4352;
    uint32_t smem_u32 = (uint32_t)__cvta_generic_to_shared(dynsm);
    const uint32_t OFF_AL = 2 * 5120 * 2;
    const uint32_t OFF_BH = OFF_AL + 2 * 5120 * 2;
    const uint32_t OFF_BL = OFF_BH + 2 * 4352 * 2;

    int tid = threadIdx.x;
    int wid = tid >> 5;
    int lane = tid & 31;
    int warp_m = wid >> 2;   // 0..1
    int warp_n = wid & 3;    // 0..3

    int row0 = blockIdx.y * 128;
    int col0 = blockIdx.x * 128;

    wmma::fragment<wmma::accumulator, 16, 16, 16, float> acc[4][2];
#pragma unroll
    for (int i = 0; i < 4; i++)
#pragma unroll
        for (int j = 0; j < 2; j++) wmma::fill_fragment(acc[i][j], 0.f);

    int kt = Kp >> 5;

    // issue loads for tile t into buffer buf
    auto issue = [&](int t, int buf) {
        int kbase = t * 32;
        int c0 = tid * 2;
#pragma unroll
        for (int u = 0; u < 2; u++) {
            int c = c0 + u;
            // A chunk: 512 chunks of 8 bf16; row = c/4, colchunk = c%4
            int arow = c >> 2, ac = (c & 3) * 8;
            size_t ga = (size_t)(row0 + arow) * Kp + kbase + ac;
            uint32_t sa = smem_u32 + (uint32_t)(buf * 5120 + arow * 40 + ac) * 2;
            cp16(sa, Ah + ga);
            cp16(sa + OFF_AL, Al + ga);
            // B chunk: 512 chunks; row = c/16, colchunk = c%16
            int brow = c >> 4, bc = (c & 15) * 8;
            size_t gb = (size_t)(kbase + brow) * Mp + col0 + bc;
            uint32_t sb = smem_u32 + OFF_BH + (uint32_t)(buf * 4352 + brow * 136 + bc) * 2;
            cp16(sb, Wh + gb);
            cp16(sb + (OFF_BL - OFF_BH), Wl + gb);
        }
        cp_commit();
    };

    issue(0, 0);
    if (kt > 1) issue(1, 1);

    int buf = 0;
    for (int t = 0; t < kt; t++) {
        if (t + 1 < kt) cp_wait<1>(); else cp_wait<0>();
        __syncthreads();

        const __nv_bfloat16* pAh = sAh + buf * 5120;
        const __nv_bfloat16* pAl = sAl + buf * 5120;
        const __nv_bfloat16* pBh = sBh + buf * 4352;
        const __nv_bfloat16* pBl = sBl + buf * 4352;

#pragma unroll
        for (int ks = 0; ks < 2; ks++) {
            wmma::fragment<wmma::matrix_b, 16, 16, 16, __nv_bfloat16, wmma::row_major> bh[2], bl[2];
#pragma unroll
            for (int j = 0; j < 2; j++) {
                wmma::load_matrix_sync(bh[j], pBh + (ks * 16) * 136 + warp_n * 32 + j * 16, 136);
                wmma::load_matrix_sync(bl[j], pBl + (ks * 16) * 136 + warp_n * 32 + j * 16, 136);
            }
#pragma unroll
            for (int i = 0; i < 4; i++) {
                wmma::fragment<wmma::matrix_a, 16, 16, 16, __nv_bfloat16, wmma::row_major> ah, al;
                wmma::load_matrix_sync(ah, pAh + (warp_m * 64 + i * 16) * 40 + ks * 16, 40);
                wmma::load_matrix_sync(al, pAl + (warp_m * 64 + i * 16) * 40 + ks * 16, 40);
#pragma unroll
                for (int j = 0; j < 2; j++) {
                    wmma::mma_sync(acc[i][j], ah, bh[j], acc[i][j]);
                    wmma::mma_sync(acc[i][j], ah, bl[j], acc[i][j]);
                    wmma::mma_sync(acc[i][j], al, bh[j], acc[i][j]);
                }
            }
        }
        __syncthreads();
        if (t + 2 < kt) issue(t + 2, buf);
        buf ^= 1;
    }

    // epilogue: stage per-warp 16x16 through smem (now free), guarded writes
    float* Cs = (float*)dynsm + wid * 272;
    int lr = lane >> 1;
    int lc0 = (lane & 1) * 8;
#pragma unroll
    for (int i = 0; i < 4; i++) {
#pragma unroll
        for (int j = 0; j < 2; j++) {
            wmma::store_matrix_sync(Cs, acc[i][j], 16, wmma::mem_row_major);
            __syncwarp();
            int r = row0 + warp_m * 64 + i * 16 + lr;
            int cb = col0 + warp_n * 32 + j * 16 + lc0;
            if (r < N) {
#pragma unroll
                for (int q = 0; q < 8; q++) {
                    int c = cb + q;
                    if (c < M) {
                        float v = Cs[lr * 16 + lc0 + q] + (bias ? bias[c] : 0.f);
                        if (relu) v = fmaxf(v, 0.f);
                        C[(size_t)r * ldc + c] = v;
                    }
                }
            }
            __syncwarp();
        }
    }
}

static void launch_hgemm(const __nv_bfloat16* Ah, const __nv_bfloat16* Al,
                         const float* W, __nv_bfloat16* Wh, __nv_bfloat16* Wl,
                         const float* bias, float* C,
                         int N, int K, int M, int Kp, int ldc, int relu) {
    int Mp = pad128(M);
    k_cvtW<<<gdiv(Kp * Mp, 256), 256>>>(W, Wh, Wl, K, M, Kp, Mp);
    dim3 grid(Mp >> 7, N >> 7);
    k_hgemm<<<grid, 256, HG_SMEM_BYTES>>>(Ah, Al, Wh, Wl, bias, C, N, Kp, Mp, M, ldc, relu);
}

// ---------------- mean pool over contiguous per-graph ranges ----------------
__global__ void k_pool(const float* __restrict__ x, const int* __restrict__ gptr,
                       float* __restrict__ pool, int F) {
    int g = blockIdx.x;
    int beg = gptr[g], end = gptr[g + 1];
    float inv = 1.f / fmaxf((float)(end - beg), 1.f);
    for (int f = threadIdx.x; f < F; f += blockDim.x) {
        float s0 = 0.f, s1 = 0.f, s2 = 0.f, s3 = 0.f;
        int i = beg;
        for (; i + 3 < end; i += 4) {
            s0 += x[(size_t)(i + 0) * F + f];
            s1 += x[(size_t)(i + 1) * F + f];
            s2 += x[(size_t)(i + 2) * F + f];
            s3 += x[(size_t)(i + 3) * F + f];
        }
        for (; i < end; i++) s0 += x[(size_t)i * F + f];
        pool[(size_t)g * F + f] = (s0 + s1 + s2 + s3) * inv;
    }
}

// single-block exclusive scan (small n), out[n] = total (for gptr)
__global__ void k_scan_ex(const int* __restrict__ in, int* __restrict__ out, int n) {
    __shared__ int wsum[32];
    __shared__ int carry_s;
    int tid = threadIdx.x;
    int lane = tid & 31, wid = tid >> 5;
    if (tid == 0) carry_s = 0;
    __syncthreads();
    for (int base = 0; base < n; base += 1024) {
        int i = base + tid;
        int v = (i < n) ? in[i] : 0;
        int s = v;
#pragma unroll
        for (int off = 1; off < 32; off <<= 1) {
            int t = __shfl_up_sync(0xffffffffu, s, off);
            if (lane >= off) s += t;
        }
        if (lane == 31) wsum[wid] = s;
        __syncthreads();
        if (wid == 0) {
            int ws = wsum[lane];
#pragma unroll
            for (int off = 1; off < 32; off <<= 1) {
                int t = __shfl_up_sync(0xffffffffu, ws, off);
                if (lane >= off) ws += t;
            }
            wsum[lane] = ws;
        }
        __syncthreads();
        int wofs = (wid > 0) ? wsum[wid - 1] : 0;
        int incl = carry_s + wofs + s;
        if (i < n) out[i] = incl - v;
        __syncthreads();
        if (tid == 1023) carry_s = incl;
        __syncthreads();
    }
    if (threadIdx.x == 0) out[n] = carry_s;
}

// ---------------- SIMT SGEMM (templated tiles, double-buffered) ----------------
template <int MH, int NH>
__global__ __launch_bounds__(256) void k_sgemm(
    const float* __restrict__ A, const float* __restrict__ W,
    const float* __restrict__ bias, float* __restrict__ C,
    int N, int K, int M, int ldc, int relu)
{
    constexpr int TBM = 64 * MH;
    constexpr int TBN = 64 * NH;
    constexpr int CA = TBM / 32;
    constexpr int TPRA = 8 / CA;
    constexpr int CB = TBN / 32;

    __shared__ float As[2][8][TBM];
    __shared__ float Bs[2][8][TBN];

    int tid = threadIdx.x;
    int row0 = blockIdx.y * TBM;
    int col0 = blockIdx.x * TBN;
    int tx = tid & 15;
    int ty = tid >> 4;

    int a_r = tid / TPRA;
    int a_k = (tid % TPRA) * CA;
    int b_k = tid >> 5;
    int b_c = (tid & 31) * CB;

    int ar = row0 + a_r;
    const float* Arow = A + (size_t)(ar < N ? ar : 0) * K;
    bool a_ok = (ar < N);

    float acc[4 * MH][4 * NH];
#pragma unroll
    for (int i = 0; i < 4 * MH; i++)
#pragma unroll
        for (int j = 0; j < 4 * NH; j++) acc[i][j] = 0.f;

    float ra[CA], rb[CB];
    int kt = (K + 7) / 8;

#pragma unroll
    for (int i = 0; i < CA; i++) {
        int kc = a_k + i;
        ra[i] = (a_ok && kc < K) ? Arow[kc] : 0.f;
    }
#pragma unroll
    for (int i = 0; i < CB; i++) {
        int bc = col0 + b_c + i;
        rb[i] = (b_k < K && bc < M) ? W[(size_t)b_k * M + bc] : 0.f;
    }
#pragma unroll
    for (int i = 0; i < CA; i++) As[0][a_k + i][a_r] = ra[i];
#pragma unroll
    for (int i = 0; i < CB; i++) Bs[0][b_k][b_c + i] = rb[i];
    __syncthreads();

    int buf = 0;
    for (int t = 0; t < kt; t++) {
        int k_next = (t + 1) * 8;
        if (t + 1 < kt) {
#pragma unroll
            for (int i = 0; i < CA; i++) {
                int kc = k_next + a_k + i;
                ra[i] = (a_ok && kc < K) ? Arow[kc] : 0.f;
            }
            int bk = k_next + b_k;
#pragma unroll
            for (int i = 0; i < CB; i++) {
                int bc = col0 + b_c + i;
                rb[i] = (bk < K && bc < M) ? W[(size_t)bk * M + bc] : 0.f;
            }
        }

#pragma unroll
        for (int kk = 0; kk < 8; kk++) {
            float af[4 * MH], bf[4 * NH];
#pragma unroll
            for (int h = 0; h < MH; h++)
#pragma unroll
                for (int i = 0; i < 4; i++)
                    af[h * 4 + i] = As[buf][kk][h * 64 + ty * 4 + i];
#pragma unroll
            for (int h = 0; h < NH; h++)
#pragma unroll
                for (int j = 0; j < 4; j++)
                    bf[h * 4 + j] = Bs[buf][kk][h * 64 + tx * 4 + j];
#pragma unroll
            for (int i = 0; i < 4 * MH; i++)
#pragma unroll
                for (int j = 0; j < 4 * NH; j++) acc[i][j] += af[i] * bf[j];
        }

        if (t + 1 < kt) {
            int nb = buf ^ 1;
#pragma unroll
            for (int i = 0; i < CA; i++) As[nb][a_k + i][a_r] = ra[i];
#pragma unroll
            for (int i = 0; i < CB; i++) Bs[nb][b_k][b_c + i] = rb[i];
            __syncthreads();
            buf = nb;
        }
    }

#pragma unroll
    for (int hm = 0; hm < MH; hm++) {
#pragma unroll
        for (int i = 0; i < 4; i++) {
            int r = row0 + hm * 64 + ty * 4 + i;
            if (r >= N) continue;
#pragma unroll
            for (int hn = 0; hn < NH; hn++) {
#pragma unroll
                for (int j = 0; j < 4; j++) {
                    int c = col0 + hn * 64 + tx * 4 + j;
                    if (c >= M) continue;
                    float v = acc[hm * 4 + i][hn * 4 + j] + (bias ? bias[c] : 0.f);
                    if (relu) v = fmaxf(v, 0.f);
                    C[(size_t)r * ldc + c] = v;
                }
            }
        }
    }
}

static void launch_sgemm(const float* A, const float* W, const float* bias, float* C,
                         int N, int K, int M, int ldc, int relu) {
    int best_bm = 128, best_bn = 128;
    double best_score = 1e30;
    for (int bm = 128; bm >= 64; bm -= 64) {
        for (int bn = 128; bn >= 64; bn -= 64) {
            double padw = (double)((long)gdiv(N, bm) * bm) * ((long)gdiv(M, bn) * bn);
            long ctas = (long)gdiv(N, bm) * gdiv(M, bn);
            double occ_pen = (ctas < 296) ? (296.0 / (double)ctas) : 1.0;
            double tile_pen = (bm == 64 ? 1.06 : 1.0) * (bn == 64 ? 1.06 : 1.0);
            double score = padw * occ_pen * tile_pen;
            if (score < best_score) { best_score = score; best_bm = bm; best_bn = bn; }
        }
    }
    dim3 grid(gdiv(M, best_bn), gdiv(N, best_bm));
    if (best_bm == 128 && best_bn == 128)      k_sgemm<2, 2><<<grid, 256>>>(A, W, bias, C, N, K, M, ldc, relu);
    else if (best_bm == 128 && best_bn == 64)  k_sgemm<2, 1><<<grid, 256>>>(A, W, bias, C, N, K, M, ldc, relu);
    else if (best_bm == 64 && best_bn == 128)  k_sgemm<1, 2><<<grid, 256>>>(A, W, bias, C, N, K, M, ldc, relu);
    else                                       k_sgemm<1, 1><<<grid, 256>>>(A, W, bias, C, N, K, M, ldc, relu);
}

// ---------------- branch orchestration ----------------
static void run_branch(const float* x0, const int* ei, int E, const int* bat, int N,
                       int F0, int F1, int F2, int F3,
                       const float* w1, const float* b1,
                       const float* w2, const float* b2,
                       const float* w3, const float* b3,
                       const float* fw1, const float* fb1,
                       const float* fw2, const float* fb2,
                       float* cat_ptr,
                       float* Y, float* A, float* Bf,
                       __nv_bfloat16* Ahb, __nv_bfloat16* Alb,
                       __nv_bfloat16* Whb, __nv_bfloat16* Wlb,
                       float* nrm, int* deg, int* cur, int* rowptr, int* csr,
                       int* bsum, int* gcnt, int* gptr, float* pool, float* fc1)
{
    const int* src = ei;
    const int* dst = ei + E;
    const int T = 256;
    int nb = gdiv(N, 1024);

    k_zero2i<<<gdiv(N, T), T>>>(deg, cur, N);              // 0
    k_hist<<<gdiv(E, T), T>>>(dst, deg, E);                // 1
    k_scan_blk<<<nb, 1024>>>(deg, rowptr, bsum, N);        // 2
    launch_sgemm(x0, w1, nullptr, Y, N, F0, F1, F1, 0);    // 3 (profiled)
    k_scan_small<<<1, 128>>>(bsum, nb);                    // 4
    k_scan_add<<<gdiv(N, T), T>>>(rowptr, bsum, N, nb);    // 5
    k_nrm<<<gdiv(N, T), T>>>(deg, nrm, N);                 // 6
    k_fill<<<gdiv(E, T), T>>>(src, dst, rowptr, cur, csr, E); // 7

    // layer 1 epilogue: A = relu(nrm*(agg(Y) + nrm*Y) + b1)
    launch_agg(Y, nrm, rowptr, csr, A, N, F1, b1, 1);

    // layer 2: split-bf16 agg(input) -> tensor-core GEMM
    int Kp1 = pad32(F1);
    launch_aggb(A, nrm, rowptr, csr, Ahb, Alb, N, F1, Kp1);
    launch_hgemm(Ahb, Alb, w2, Whb, Wlb, b2, Bf, N, F1, F2, Kp1, F2, 1);

    // layer 3
    int Kp2 = pad32(F2);
    launch_aggb(Bf, nrm, rowptr, csr, Ahb, Alb, N, F2, Kp2);
    launch_hgemm(Ahb, Alb, w3, Whb, Wlb, b3, A, N, F2, F3, Kp2, F3, 1);

    // mean pool (batch sorted -> contiguous ranges)
    k_zeroi<<<1, 256>>>(gcnt, 256);
    k_hist<<<gdiv(N, T), T>>>(bat, gcnt, N);
    k_scan_ex<<<1, 1024>>>(gcnt, gptr, 256);
    k_pool<<<256, 256>>>(A, gptr, pool, F3);

    // fc1 (relu), fc2 -> concat slice (ldc=256)
    launch_sgemm(pool, fw1, fb1, fc1, 256, F3, 1024, 1024, 1);
    launch_sgemm(fc1, fw2, fb2, cat_ptr, 256, 1024, 128, 256, 0);
}

extern "C" void kernel_launch(void* const* d_in, const int* in_sizes, int n_in,
                              void* d_out, int out_size)
{
    static bool smem_set = false;
    if (!smem_set) {
        cudaFuncSetAttribute(k_hgemm, cudaFuncAttributeMaxDynamicSharedMemorySize, HG_SMEM_BYTES);
        smem_set = true;
    }

    float *Y, *A, *Bf, *nrm, *pool, *fc1, *cat, *head;
    __nv_bfloat16 *Ahb, *Alb, *Whb, *Wlb;
    int *deg, *cur, *rowptr, *csr, *bsum, *gcnt, *gptr;
    cudaGetSymbolAddress((void**)&Y,      g_Y);
    cudaGetSymbolAddress((void**)&A,      g_A);
    cudaGetSymbolAddress((void**)&Bf,     g_B);
    cudaGetSymbolAddress((void**)&Ahb,    g_Ah);
    cudaGetSymbolAddress((void**)&Alb,    g_Al);
    cudaGetSymbolAddress((void**)&Whb,    g_Wh);
    cudaGetSymbolAddress((void**)&Wlb,    g_Wl);
    cudaGetSymbolAddress((void**)&nrm,    g_nrm);
    cudaGetSymbolAddress((void**)&deg,    g_deg);
    cudaGetSymbolAddress((void**)&cur,    g_cur);
    cudaGetSymbolAddress((void**)&rowptr, g_rowptr);
    cudaGetSymbolAddress((void**)&csr,    g_csr);
    cudaGetSymbolAddress((void**)&bsum,   g_bsum);
    cudaGetSymbolAddress((void**)&gcnt,   g_gcnt);
    cudaGetSymbolAddress((void**)&gptr,   g_gptr);
    cudaGetSymbolAddress((void**)&pool,   g_pool);
    cudaGetSymbolAddress((void**)&fc1,    g_fc1);
    cudaGetSymbolAddress((void**)&cat,    g_cat);
    cudaGetSymbolAddress((void**)&head,   g_head);

    const float* mol_x  = (const float*)d_in[0];
    const int*   mol_ei = (const int*)  d_in[1];
    const int*   mol_b  = (const int*)  d_in[2];
    const float* pro_x  = (const float*)d_in[3];
    const int*   pro_ei = (const int*)  d_in[4];
    const int*   pro_b  = (const int*)  d_in[5];

    int N_mol = in_sizes[2];
    int E_mol = in_sizes[1] / 2;
    int F_mol = in_sizes[0] / N_mol;     // 78
    int N_pro = in_sizes[5];
    int E_pro = in_sizes[4] / 2;
    int F_pro = in_sizes[3] / N_pro;     // 54

    const float* mw1  = (const float*)d_in[6];
    const float* mb1  = (const float*)d_in[7];
    const float* mw2  = (const float*)d_in[8];
    const float* mb2  = (const float*)d_in[9];
    const float* mw3  = (const float*)d_in[10];
    const float* mb3  = (const float*)d_in[11];
    const float* mfw1 = (const float*)d_in[12];
    const float* mfb1 = (const float*)d_in[13];
    const float* mfw2 = (const float*)d_in[14];
    const float* mfb2 = (const float*)d_in[15];
    const float* pw1  = (const float*)d_in[16];
    const float* pb1  = (const float*)d_in[17];
    const float* pw2  = (const float*)d_in[18];
    const float* pb2  = (const float*)d_in[19];
    const float* pw3  = (const float*)d_in[20];
    const float* pb3  = (const float*)d_in[21];
    const float* pfw1 = (const float*)d_in[22];
    const float* pfb1 = (const float*)d_in[23];
    const float* pfw2 = (const float*)d_in[24];
    const float* pfb2 = (const float*)d_in[25];
    const float* fc1w = (const float*)d_in[26];
    const float* fc1b = (const float*)d_in[27];
    const float* fc2w = (const float*)d_in[28];
    const float* fc2b = (const float*)d_in[29];
    const float* outw = (const float*)d_in[30];
    const float* outb = (const float*)d_in[31];

    // protein branch (heavy): 54 -> 54 -> 108 -> 216; cat[:,128:256]
    run_branch(pro_x, pro_ei, E_pro, pro_b, N_pro,
               F_pro, F_pro, 2 * F_pro, 4 * F_pro,
               pw1, pb1, pw2, pb2, pw3, pb3,
               pfw1, pfb1, pfw2, pfb2,
               cat + 128,
               Y, A, Bf, Ahb, Alb, Whb, Wlb,
               nrm, deg, cur, rowptr, csr, bsum, gcnt, gptr, pool, fc1);

    // molecule branch: 78 -> 78 -> 156 -> 312; cat[:,0:128]
    run_branch(mol_x, mol_ei, E_mol, mol_b, N_mol,
               F_mol, F_mol, 2 * F_mol, 4 * F_mol,
               mw1, mb1, mw2, mb2, mw3, mb3,
               mfw1, mfb1, mfw2, mfb2,
               cat,
               Y, A, Bf, Ahb, Alb, Whb, Wlb,
               nrm, deg, cur, rowptr, csr, bsum, gcnt, gptr, pool, fc1);

    // combined head
    launch_sgemm(cat,  fc1w, fc1b, fc1,           256, 256,  1024, 1024, 1);
    launch_sgemm(fc1,  fc2w, fc2b, head,          256, 1024, 512,  512,  1);
    launch_sgemm(head, outw, outb, (float*)d_out, 256, 512,  1,    1,    0);
}

// round 7
// speedup vs baseline: 1.2603x; 1.2603x over previous
#include <cuda_runtime.h>
#include <math.h>
#include <stdint.h>

// ---------------- scratch (device globals; no allocations) ----------------
#define MAXN 76800
#define MAXE 768000
#define MAXNF (76800u * 216u)
#define MOLN 10240
#define MOLE 40960
#define MOLNF (10240u * 312u)

// protein-branch buffers
__device__ float g_Y[MAXNF];
__device__ float g_A[MAXNF];
__device__ float g_B[MAXNF];
__device__ float g_nrm[MAXN];
__device__ int   g_deg[MAXN];
__device__ int   g_cur[MAXN];
__device__ int   g_rowptr[MAXN + 1];
__device__ int   g_csr[MAXE];
__device__ int   g_bsum[128];
__device__ int   g_gcnt[256];
__device__ int   g_gptr[257];
__device__ float g_pool[256 * 312];
__device__ float g_fc1[256 * 1024];
// molecule-branch buffers (private, for stream overlap)
__device__ float m_Y[MOLNF];
__device__ float m_A[MOLNF];
__device__ float m_B[MOLNF];
__device__ float m_nrm[MOLN];
__device__ int   m_deg[MOLN];
__device__ int   m_cur[MOLN];
__device__ int   m_rowptr[MOLN + 1];
__device__ int   m_csr[MOLE];
__device__ int   m_bsum[128];
__device__ int   m_gcnt[256];
__device__ int   m_gptr[257];
__device__ float m_pool[256 * 312];
__device__ float m_fc1[256 * 1024];
// shared tail
__device__ float g_cat[256 * 256];
__device__ float g_head[256 * 512];

static inline int gdiv(int n, int d) { return (n + d - 1) / d; }

// ---------------- small utility kernels ----------------
__global__ void k_zero2i(int* a, int* b, int n) {
    int i = blockIdx.x * blockDim.x + threadIdx.x;
    if (i < n) { a[i] = 0; b[i] = 0; }
}

__global__ void k_zeroi(int* a, int n) {
    int i = blockIdx.x * blockDim.x + threadIdx.x;
    if (i < n) a[i] = 0;
}

__global__ void k_hist(const int* __restrict__ idx, int* __restrict__ acc, int n) {
    int i = blockIdx.x * blockDim.x + threadIdx.x;
    if (i < n) atomicAdd(&acc[idx[i]], 1);
}

__global__ void k_nrm(const int* __restrict__ deg, float* __restrict__ nrm, int n) {
    int i = blockIdx.x * blockDim.x + threadIdx.x;
    if (i < n) nrm[i] = rsqrtf((float)deg[i] + 1.f);
}

// ---- multi-block exclusive scan ----
__global__ void k_scan_blk(const int* __restrict__ in, int* __restrict__ out,
                           int* __restrict__ bsum, int n) {
    __shared__ int wsum[32];
    int tid = threadIdx.x;
    int lane = tid & 31, wid = tid >> 5;
    int i = blockIdx.x * 1024 + tid;
    int v = (i < n) ? in[i] : 0;
    int s = v;
#pragma unroll
    for (int off = 1; off < 32; off <<= 1) {
        int t = __shfl_up_sync(0xffffffffu, s, off);
        if (lane >= off) s += t;
    }
    if (lane == 31) wsum[wid] = s;
    __syncthreads();
    if (wid == 0) {
        int ws = wsum[lane];
#pragma unroll
        for (int off = 1; off < 32; off <<= 1) {
            int t = __shfl_up_sync(0xffffffffu, ws, off);
            if (lane >= off) ws += t;
        }
        wsum[lane] = ws;
    }
    __syncthreads();
    int wofs = (wid > 0) ? wsum[wid - 1] : 0;
    int incl = wofs + s;
    if (i < n) out[i] = incl - v;
    if (tid == 1023) bsum[blockIdx.x] = incl;
}

__global__ void k_scan_small(int* __restrict__ b, int nb) {
    __shared__ int wsum[4];
    int tid = threadIdx.x;
    int lane = tid & 31, wid = tid >> 5;
    int v = (tid < nb) ? b[tid] : 0;
    int s = v;
#pragma unroll
    for (int off = 1; off < 32; off <<= 1) {
        int t = __shfl_up_sync(0xffffffffu, s, off);
        if (lane >= off) s += t;
    }
    if (lane == 31) wsum[wid] = s;
    __syncthreads();
    if (tid == 0) {
        int c = 0;
        for (int w = 0; w < 4; w++) { int t = wsum[w]; wsum[w] = c; c += t; }
    }
    __syncthreads();
    int excl = wsum[wid] + s - v;
    __syncthreads();
    if (tid < nb) b[tid] = excl;
    if (tid == nb - 1) b[nb] = excl + v;
}

__global__ void k_scan_add(int* __restrict__ out, const int* __restrict__ bsum,
                           int n, int nb) {
    int i = blockIdx.x * blockDim.x + threadIdx.x;
    if (i < n) out[i] += bsum[i >> 10];
    if (i == 0) out[n] = bsum[nb];
}

// single-block exclusive scan (small n), out[n] = total (for gptr)
__global__ void k_scan_ex(const int* __restrict__ in, int* __restrict__ out, int n) {
    __shared__ int wsum[32];
    __shared__ int carry_s;
    int tid = threadIdx.x;
    int lane = tid & 31, wid = tid >> 5;
    if (tid == 0) carry_s = 0;
    __syncthreads();
    for (int base = 0; base < n; base += 1024) {
        int i = base + tid;
        int v = (i < n) ? in[i] : 0;
        int s = v;
#pragma unroll
        for (int off = 1; off < 32; off <<= 1) {
            int t = __shfl_up_sync(0xffffffffu, s, off);
            if (lane >= off) s += t;
        }
        if (lane == 31) wsum[wid] = s;
        __syncthreads();
        if (wid == 0) {
            int ws = wsum[lane];
#pragma unroll
            for (int off = 1; off < 32; off <<= 1) {
                int t = __shfl_up_sync(0xffffffffu, ws, off);
                if (lane >= off) ws += t;
            }
            wsum[lane] = ws;
        }
        __syncthreads();
        int wofs = (wid > 0) ? wsum[wid - 1] : 0;
        int incl = carry_s + wofs + s;
        if (i < n) out[i] = incl - v;
        __syncthreads();
        if (tid == 1023) carry_s = incl;
        __syncthreads();
    }
    if (threadIdx.x == 0) out[n] = carry_s;
}

__global__ void k_fill(const int* __restrict__ src, const int* __restrict__ dst,
                       const int* __restrict__ rowptr, int* __restrict__ cur,
                       int* __restrict__ csr, int E) {
    int e = blockIdx.x * blockDim.x + threadIdx.x;
    if (e >= E) return;
    int d = dst[e];
    int p = rowptr[d] + atomicAdd(&cur[d], 1);
    csr[p] = src[e];
}

// ---------------- aggregation: y_i = nrm_i*(sum nrm_s x_s + nrm_i x_i) [+bias][relu]
template <int NF>
__global__ void k_agg(const float* __restrict__ x, const float* __restrict__ nrm,
                      const int* __restrict__ rowptr, const int* __restrict__ csr,
                      float* __restrict__ y, int N, int F,
                      const float* __restrict__ bias, int dorelu) {
    int warp = (blockIdx.x * blockDim.x + threadIdx.x) >> 5;
    int lane = threadIdx.x & 31;
    if (warp >= N) return;
    int beg = rowptr[warp], end = rowptr[warp + 1];
    float ni = nrm[warp];

    float acc[NF];
#pragma unroll
    for (int j = 0; j < NF; j++) acc[j] = 0.f;

    int e = beg;
    for (; e + 1 < end; e += 2) {
        int s0 = csr[e], s1 = csr[e + 1];
        float n0 = nrm[s0], n1 = nrm[s1];
        const float* x0 = x + (size_t)s0 * F;
        const float* x1 = x + (size_t)s1 * F;
#pragma unroll
        for (int j = 0; j < NF; j++) {
            int f = lane + 32 * j;
            if (f < F) acc[j] += x0[f] * n0 + x1[f] * n1;
        }
    }
    if (e < end) {
        int s0 = csr[e];
        float n0 = nrm[s0];
        const float* x0 = x + (size_t)s0 * F;
#pragma unroll
        for (int j = 0; j < NF; j++) {
            int f = lane + 32 * j;
            if (f < F) acc[j] += x0[f] * n0;
        }
    }
    const float* xi = x + (size_t)warp * F;
    float* yi = y + (size_t)warp * F;
#pragma unroll
    for (int j = 0; j < NF; j++) {
        int f = lane + 32 * j;
        if (f < F) {
            float v = ni * (acc[j] + ni * xi[f]);
            if (bias) v += bias[f];
            if (dorelu) v = fmaxf(v, 0.f);
            yi[f] = v;
        }
    }
}

static void launch_agg(const float* x, const float* nrm, const int* rp, const int* csr,
                       float* y, int N, int F, const float* bias, int dorelu,
                       cudaStream_t st) {
    int blocks = gdiv(N, 8);
    int nf = gdiv(F, 32);
    switch (nf) {
        case 2: k_agg<2><<<blocks, 256, 0, st>>>(x, nrm, rp, csr, y, N, F, bias, dorelu); break;
        case 3: k_agg<3><<<blocks, 256, 0, st>>>(x, nrm, rp, csr, y, N, F, bias, dorelu); break;
        case 4: k_agg<4><<<blocks, 256, 0, st>>>(x, nrm, rp, csr, y, N, F, bias, dorelu); break;
        case 5: k_agg<5><<<blocks, 256, 0, st>>>(x, nrm, rp, csr, y, N, F, bias, dorelu); break;
        default: k_agg<8><<<blocks, 256, 0, st>>>(x, nrm, rp, csr, y, N, F, bias, dorelu); break;
    }
}

// ---------------- mean pool over contiguous per-graph ranges ----------------
__global__ void k_pool(const float* __restrict__ x, const int* __restrict__ gptr,
                       float* __restrict__ pool, int F) {
    int g = blockIdx.x;
    int beg = gptr[g], end = gptr[g + 1];
    float inv = 1.f / fmaxf((float)(end - beg), 1.f);
    for (int f = threadIdx.x; f < F; f += blockDim.x) {
        float s0 = 0.f, s1 = 0.f, s2 = 0.f, s3 = 0.f;
        int i = beg;
        for (; i + 3 < end; i += 4) {
            s0 += x[(size_t)(i + 0) * F + f];
            s1 += x[(size_t)(i + 1) * F + f];
            s2 += x[(size_t)(i + 2) * F + f];
            s3 += x[(size_t)(i + 3) * F + f];
        }
        for (; i < end; i++) s0 += x[(size_t)i * F + f];
        pool[(size_t)g * F + f] = (s0 + s1 + s2 + s3) * inv;
    }
}

// ---------------- SIMT SGEMM (templated tiles, double-buffered) ----------------
template <int MH, int NH>
__global__ __launch_bounds__(256) void k_sgemm(
    const float* __restrict__ A, const float* __restrict__ W,
    const float* __restrict__ bias, float* __restrict__ C,
    int N, int K, int M, int ldc, int relu)
{
    constexpr int TBM = 64 * MH;
    constexpr int TBN = 64 * NH;
    constexpr int CA = TBM / 32;
    constexpr int TPRA = 8 / CA;
    constexpr int CB = TBN / 32;

    __shared__ float As[2][8][TBM];
    __shared__ float Bs[2][8][TBN];

    int tid = threadIdx.x;
    int row0 = blockIdx.y * TBM;
    int col0 = blockIdx.x * TBN;
    int tx = tid & 15;
    int ty = tid >> 4;

    int a_r = tid / TPRA;
    int a_k = (tid % TPRA) * CA;
    int b_k = tid >> 5;
    int b_c = (tid & 31) * CB;

    int ar = row0 + a_r;
    const float* Arow = A + (size_t)(ar < N ? ar : 0) * K;
    bool a_ok = (ar < N);

    float acc[4 * MH][4 * NH];
#pragma unroll
    for (int i = 0; i < 4 * MH; i++)
#pragma unroll
        for (int j = 0; j < 4 * NH; j++) acc[i][j] = 0.f;

    float ra[CA], rb[CB];
    int kt = (K + 7) / 8;

#pragma unroll
    for (int i = 0; i < CA; i++) {
        int kc = a_k + i;
        ra[i] = (a_ok && kc < K) ? Arow[kc] : 0.f;
    }
#pragma unroll
    for (int i = 0; i < CB; i++) {
        int bc = col0 + b_c + i;
        rb[i] = (b_k < K && bc < M) ? W[(size_t)b_k * M + bc] : 0.f;
    }
#pragma unroll
    for (int i = 0; i < CA; i++) As[0][a_k + i][a_r] = ra[i];
#pragma unroll
    for (int i = 0; i < CB; i++) Bs[0][b_k][b_c + i] = rb[i];
    __syncthreads();

    int buf = 0;
    for (int t = 0; t < kt; t++) {
        int k_next = (t + 1) * 8;
        if (t + 1 < kt) {
#pragma unroll
            for (int i = 0; i < CA; i++) {
                int kc = k_next + a_k + i;
                ra[i] = (a_ok && kc < K) ? Arow[kc] : 0.f;
            }
            int bk = k_next + b_k;
#pragma unroll
            for (int i = 0; i < CB; i++) {
                int bc = col0 + b_c + i;
                rb[i] = (bk < K && bc < M) ? W[(size_t)bk * M + bc] : 0.f;
            }
        }

#pragma unroll
        for (int kk = 0; kk < 8; kk++) {
            float af[4 * MH], bf[4 * NH];
#pragma unroll
            for (int h = 0; h < MH; h++)
#pragma unroll
                for (int i = 0; i < 4; i++)
                    af[h * 4 + i] = As[buf][kk][h * 64 + ty * 4 + i];
#pragma unroll
            for (int h = 0; h < NH; h++)
#pragma unroll
                for (int j = 0; j < 4; j++)
                    bf[h * 4 + j] = Bs[buf][kk][h * 64 + tx * 4 + j];
#pragma unroll
            for (int i = 0; i < 4 * MH; i++)
#pragma unroll
                for (int j = 0; j < 4 * NH; j++) acc[i][j] += af[i] * bf[j];
        }

        if (t + 1 < kt) {
            int nb = buf ^ 1;
#pragma unroll
            for (int i = 0; i < CA; i++) As[nb][a_k + i][a_r] = ra[i];
#pragma unroll
            for (int i = 0; i < CB; i++) Bs[nb][b_k][b_c + i] = rb[i];
            __syncthreads();
            buf = nb;
        }
    }

#pragma unroll
    for (int hm = 0; hm < MH; hm++) {
#pragma unroll
        for (int i = 0; i < 4; i++) {
            int r = row0 + hm * 64 + ty * 4 + i;
            if (r >= N) continue;
#pragma unroll
            for (int hn = 0; hn < NH; hn++) {
#pragma unroll
                for (int j = 0; j < 4; j++) {
                    int c = col0 + hn * 64 + tx * 4 + j;
                    if (c >= M) continue;
                    float v = acc[hm * 4 + i][hn * 4 + j] + (bias ? bias[c] : 0.f);
                    if (relu) v = fmaxf(v, 0.f);
                    C[(size_t)r * ldc + c] = v;
                }
            }
        }
    }
}

static void launch_sgemm(const float* A, const float* W, const float* bias, float* C,
                         int N, int K, int M, int ldc, int relu, cudaStream_t st) {
    int best_bm = 128, best_bn = 128;
    double best_score = 1e30;
    for (int bm = 128; bm >= 64; bm -= 64) {
        for (int bn = 128; bn >= 64; bn -= 64) {
            double padw = (double)((long)gdiv(N, bm) * bm) * ((long)gdiv(M, bn) * bn);
            long ctas = (long)gdiv(N, bm) * gdiv(M, bn);
            double occ_pen = (ctas < 296) ? (296.0 / (double)ctas) : 1.0;
            double tile_pen = (bm == 64 ? 1.06 : 1.0) * (bn == 64 ? 1.06 : 1.0);
            double score = padw * occ_pen * tile_pen;
            if (score < best_score) { best_score = score; best_bm = bm; best_bn = bn; }
        }
    }
    dim3 grid(gdiv(M, best_bn), gdiv(N, best_bm));
    if (best_bm == 128 && best_bn == 128)      k_sgemm<2, 2><<<grid, 256, 0, st>>>(A, W, bias, C, N, K, M, ldc, relu);
    else if (best_bm == 128 && best_bn == 64)  k_sgemm<2, 1><<<grid, 256, 0, st>>>(A, W, bias, C, N, K, M, ldc, relu);
    else if (best_bm == 64 && best_bn == 128)  k_sgemm<1, 2><<<grid, 256, 0, st>>>(A, W, bias, C, N, K, M, ldc, relu);
    else                                       k_sgemm<1, 1><<<grid, 256, 0, st>>>(A, W, bias, C, N, K, M, ldc, relu);
}

// ---------------- branch orchestration ----------------
static void run_branch(const float* x0, const int* ei, int E, const int* bat, int N,
                       int F0, int F1, int F2, int F3,
                       const float* w1, const float* b1,
                       const float* w2, const float* b2,
                       const float* w3, const float* b3,
                       const float* fw1, const float* fb1,
                       const float* fw2, const float* fb2,
                       float* cat_ptr,
                       float* Y, float* A, float* Bf,
                       float* nrm, int* deg, int* cur, int* rowptr, int* csr,
                       int* bsum, int* gcnt, int* gptr, float* pool, float* fc1,
                       cudaStream_t st)
{
    const int* src = ei;
    const int* dst = ei + E;
    const int T = 256;
    int nb = gdiv(N, 1024);

    k_zero2i<<<gdiv(N, T), T, 0, st>>>(deg, cur, N);
    k_hist<<<gdiv(E, T), T, 0, st>>>(dst, deg, E);
    k_scan_blk<<<nb, 1024, 0, st>>>(deg, rowptr, bsum, N);
    launch_sgemm(x0, w1, nullptr, Y, N, F0, F1, F1, 0, st);
    k_scan_small<<<1, 128, 0, st>>>(bsum, nb);
    k_scan_add<<<gdiv(N, T), T, 0, st>>>(rowptr, bsum, N, nb);
    k_nrm<<<gdiv(N, T), T, 0, st>>>(deg, nrm, N);
    k_fill<<<gdiv(E, T), T, 0, st>>>(src, dst, rowptr, cur, csr, E);

    // layer 1 epilogue: A = relu(nrm*(agg(Y) + nrm*Y) + b1)
    launch_agg(Y, nrm, rowptr, csr, A, N, F1, b1, 1, st);

    // layer 2
    launch_agg(A, nrm, rowptr, csr, Y, N, F1, nullptr, 0, st);
    launch_sgemm(Y, w2, b2, Bf, N, F1, F2, F2, 1, st);

    // layer 3
    launch_agg(Bf, nrm, rowptr, csr, Y, N, F2, nullptr, 0, st);
    launch_sgemm(Y, w3, b3, A, N, F2, F3, F3, 1, st);

    // mean pool (batch sorted -> contiguous ranges)
    k_zeroi<<<1, 256, 0, st>>>(gcnt, 256);
    k_hist<<<gdiv(N, T), T, 0, st>>>(bat, gcnt, N);
    k_scan_ex<<<1, 1024, 0, st>>>(gcnt, gptr, 256);
    k_pool<<<256, 256, 0, st>>>(A, gptr, pool, F3);

    // fc1 (relu), fc2 -> concat slice (ldc=256)
    launch_sgemm(pool, fw1, fb1, fc1, 256, F3, 1024, 1024, 1, st);
    launch_sgemm(fc1, fw2, fb2, cat_ptr, 256, 1024, 128, 256, 0, st);
}

extern "C" void kernel_launch(void* const* d_in, const int* in_sizes, int n_in,
                              void* d_out, int out_size)
{
    static cudaStream_t s2 = nullptr;
    static cudaEvent_t evFork = nullptr, evJoin = nullptr;
    if (!s2) {
        cudaStreamCreateWithFlags(&s2, cudaStreamNonBlocking);
        cudaEventCreateWithFlags(&evFork, cudaEventDisableTiming);
        cudaEventCreateWithFlags(&evJoin, cudaEventDisableTiming);
    }

    float *Y, *A, *Bf, *nrm, *pool, *fc1;
    int *deg, *cur, *rowptr, *csr, *bsum, *gcnt, *gptr;
    float *mY, *mA, *mBf, *mnrm, *mpool, *mfc1;
    int *mdeg, *mcur, *mrowptr, *mcsr, *mbsum, *mgcnt, *mgptr;
    float *cat, *head;
    cudaGetSymbolAddress((void**)&Y,       g_Y);
    cudaGetSymbolAddress((void**)&A,       g_A);
    cudaGetSymbolAddress((void**)&Bf,      g_B);
    cudaGetSymbolAddress((void**)&nrm,     g_nrm);
    cudaGetSymbolAddress((void**)&deg,     g_deg);
    cudaGetSymbolAddress((void**)&cur,     g_cur);
    cudaGetSymbolAddress((void**)&rowptr,  g_rowptr);
    cudaGetSymbolAddress((void**)&csr,     g_csr);
    cudaGetSymbolAddress((void**)&bsum,    g_bsum);
    cudaGetSymbolAddress((void**)&gcnt,    g_gcnt);
    cudaGetSymbolAddress((void**)&gptr,    g_gptr);
    cudaGetSymbolAddress((void**)&pool,    g_pool);
    cudaGetSymbolAddress((void**)&fc1,     g_fc1);
    cudaGetSymbolAddress((void**)&mY,      m_Y);
    cudaGetSymbolAddress((void**)&mA,      m_A);
    cudaGetSymbolAddress((void**)&mBf,     m_B);
    cudaGetSymbolAddress((void**)&mnrm,    m_nrm);
    cudaGetSymbolAddress((void**)&mdeg,    m_deg);
    cudaGetSymbolAddress((void**)&mcur,    m_cur);
    cudaGetSymbolAddress((void**)&mrowptr, m_rowptr);
    cudaGetSymbolAddress((void**)&mcsr,    m_csr);
    cudaGetSymbolAddress((void**)&mbsum,   m_bsum);
    cudaGetSymbolAddress((void**)&mgcnt,   m_gcnt);
    cudaGetSymbolAddress((void**)&mgptr,   m_gptr);
    cudaGetSymbolAddress((void**)&mpool,   m_pool);
    cudaGetSymbolAddress((void**)&mfc1,    m_fc1);
    cudaGetSymbolAddress((void**)&cat,     g_cat);
    cudaGetSymbolAddress((void**)&head,    g_head);

    const float* mol_x  = (const float*)d_in[0];
    const int*   mol_ei = (const int*)  d_in[1];
    const int*   mol_b  = (const int*)  d_in[2];
    const float* pro_x  = (const float*)d_in[3];
    const int*   pro_ei = (const int*)  d_in[4];
    const int*   pro_b  = (const int*)  d_in[5];

    int N_mol = in_sizes[2];
    int E_mol = in_sizes[1] / 2;
    int F_mol = in_sizes[0] / N_mol;     // 78
    int N_pro = in_sizes[5];
    int E_pro = in_sizes[4] / 2;
    int F_pro = in_sizes[3] / N_pro;     // 54

    const float* mw1  = (const float*)d_in[6];
    const float* mb1  = (const float*)d_in[7];
    const float* mw2  = (const float*)d_in[8];
    const float* mb2  = (const float*)d_in[9];
    const float* mw3  = (const float*)d_in[10];
    const float* mb3  = (const float*)d_in[11];
    const float* mfw1 = (const float*)d_in[12];
    const float* mfb1 = (const float*)d_in[13];
    const float* mfw2 = (const float*)d_in[14];
    const float* mfb2 = (const float*)d_in[15];
    const float* pw1  = (const float*)d_in[16];
    const float* pb1  = (const float*)d_in[17];
    const float* pw2  = (const float*)d_in[18];
    const float* pb2  = (const float*)d_in[19];
    const float* pw3  = (const float*)d_in[20];
    const float* pb3  = (const float*)d_in[21];
    const float* pfw1 = (const float*)d_in[22];
    const float* pfb1 = (const float*)d_in[23];
    const float* pfw2 = (const float*)d_in[24];
    const float* pfb2 = (const float*)d_in[25];
    const float* fc1w = (const float*)d_in[26];
    const float* fc1b = (const float*)d_in[27];
    const float* fc2w = (const float*)d_in[28];
    const float* fc2b = (const float*)d_in[29];
    const float* outw = (const float*)d_in[30];
    const float* outb = (const float*)d_in[31];

    // fork: mol branch on s2, pro branch on legacy stream
    cudaEventRecord(evFork, 0);
    cudaStreamWaitEvent(s2, evFork, 0);

    // molecule branch (s2): 78 -> 78 -> 156 -> 312; cat[:,0:128]
    run_branch(mol_x, mol_ei, E_mol, mol_b, N_mol,
               F_mol, F_mol, 2 * F_mol, 4 * F_mol,
               mw1, mb1, mw2, mb2, mw3, mb3,
               mfw1, mfb1, mfw2, mfb2,
               cat,
               mY, mA, mBf, mnrm, mdeg, mcur, mrowptr, mcsr,
               mbsum, mgcnt, mgptr, mpool, mfc1, s2);

    // protein branch (legacy stream): 54 -> 54 -> 108 -> 216; cat[:,128:256]
    run_branch(pro_x, pro_ei, E_pro, pro_b, N_pro,
               F_pro, F_pro, 2 * F_pro, 4 * F_pro,
               pw1, pb1, pw2, pb2, pw3, pb3,
               pfw1, pfb1, pfw2, pfb2,
               cat + 128,
               Y, A, Bf, nrm, deg, cur, rowptr, csr,
               bsum, gcnt, gptr, pool, fc1, 0);

    // join: head waits for mol branch
    cudaEventRecord(evJoin, s2);
    cudaStreamWaitEvent(0, evJoin, 0);

    // combined head on legacy stream
    launch_sgemm(cat,  fc1w, fc1b, fc1,           256, 256,  1024, 1024, 1, 0);
    launch_sgemm(fc1,  fc2w, fc2b, head,          256, 1024, 512,  512,  1, 0);
    launch_sgemm(head, outw, outb, (float*)d_out, 256, 512,  1,    1,    0, 0);
}